// round 5
// baseline (speedup 1.0000x reference)
#include <cuda_runtime.h>
#include <cstdint>

// ---------------------------------------------------------------------------
// GAT layer, algebraically reduced:
//   softmax_j(dst[i] + src[j] + c, masked by adj)
//     == adj[i,j]*E[j] / sum_j adj[i,j]*E[j]     (i-only terms cancel)
//   out[b,i,:] = (adj @ (E*h_sum)) / (N * (adj @ E))
// Heavy op: per-batch [4096x4096]@[4096x80] via legacy mma.sync fp16
// (tcgen05 rejected by the toolchain's sm_103 ptxas target).
// fp16 mantissa == tf32 mantissa -> same accuracy as the passing R2 kernel.
// ---------------------------------------------------------------------------

#define BATCH 4
#define NNODE 4096
#define DD    256
#define NP    80          // 64 h_sum cols + 1 E col + 15 zero pad
#define BM    128
#define BK    32
#define SA    80          // A smem row stride bytes (64B data + 16B pad)
#define SB    80

__device__ float d_Mred[NP * DD];           // [c][d] (rows 65..79 zero)
__device__ float d_biasv[NP];
__device__ float d_y[16384 * NP];           // projection output
__device__ float d_gt[BATCH * NP * NNODE];  // [b][c][j] transformed, transposed
__device__ float d_srcmax[BATCH];
__device__ float d_E[16384];

// ------------------------------ helpers -----------------------------------
__device__ __forceinline__ unsigned su32(const void* p) {
    return (unsigned)__cvta_generic_to_shared(p);
}
__device__ __forceinline__ unsigned pack2(float lo, float hi) {
    unsigned d;
    asm("cvt.rn.f16x2.f32 %0, %1, %2;" : "=r"(d) : "f"(hi), "f"(lo));
    return d;
}
__device__ __forceinline__ void ldsm4(unsigned* r, unsigned a) {
    asm volatile("ldmatrix.sync.aligned.m8n8.x4.shared.b16 {%0,%1,%2,%3}, [%4];"
                 : "=r"(r[0]), "=r"(r[1]), "=r"(r[2]), "=r"(r[3]) : "r"(a));
}
__device__ __forceinline__ void mma16(float* d, const unsigned* a, const unsigned* b) {
    asm volatile("mma.sync.aligned.m16n8k16.row.col.f32.f16.f16.f32 "
                 "{%0,%1,%2,%3}, {%4,%5,%6,%7}, {%8,%9}, {%0,%1,%2,%3};"
                 : "+f"(d[0]), "+f"(d[1]), "+f"(d[2]), "+f"(d[3])
                 : "r"(a[0]), "r"(a[1]), "r"(a[2]), "r"(a[3]),
                   "r"(b[0]), "r"(b[1]));
}

// ------------------------------ prep --------------------------------------
__global__ void prep_kernel(const float* __restrict__ W_fc,
                            const float* __restrict__ b_fc,
                            const float* __restrict__ W_attn) {
    __shared__ float ws[256];
    const int tid = threadIdx.x;
    {
        int h = tid >> 6, o = tid & 63;
        ws[tid] = 0.25f * (W_attn[       h * 128 + o] +
                           W_attn[ 512 + h * 128 + o] +
                           W_attn[1024 + h * 128 + o] +
                           W_attn[1536 + h * 128 + o]);
    }
    __syncthreads();
    for (int idx = tid; idx < NP * DD; idx += 256) {
        int c = idx / DD, d = idx - c * DD;
        float v = 0.f;
        if (c < 64) {
            v = W_fc[c * DD + d] + W_fc[(64 + c) * DD + d] +
                W_fc[(128 + c) * DD + d] + W_fc[(192 + c) * DD + d];
        } else if (c == 64) {
            for (int r = 0; r < 256; r++) v += W_fc[r * DD + d] * ws[r];
        }
        d_Mred[idx] = v;
    }
    if (tid < NP) {
        float v = 0.f;
        if (tid < 64) {
            v = b_fc[tid] + b_fc[64 + tid] + b_fc[128 + tid] + b_fc[192 + tid];
        } else if (tid == 64) {
            for (int r = 0; r < 256; r++) v += b_fc[r] * ws[r];
        }
        d_biasv[tid] = v;
    }
}

// --------------------------- per-batch src max -----------------------------
__global__ void srcmax_kernel() {
    __shared__ float red[256];
    const int b = blockIdx.x, tid = threadIdx.x;
    float m = -1e30f;
    for (int j = tid; j < NNODE; j += 256)
        m = fmaxf(m, d_y[((long)b * NNODE + j) * NP + 64]);
    red[tid] = m; __syncthreads();
    for (int s = 128; s > 0; s >>= 1) {
        if (tid < s) red[tid] = fmaxf(red[tid], red[tid + s]);
        __syncthreads();
    }
    if (tid == 0) d_srcmax[b] = red[0];
}

// --------------------------- E = exp(src - max) ----------------------------
__global__ void e_kernel() {
    const int i = blockIdx.x * 256 + threadIdx.x;
    const int b = i >> 12;
    d_E[i] = __expf(d_y[(long)i * NP + 64] - d_srcmax[b]);
}

// ------------- transform -> gt (transposed, 512 small blocks) --------------
// Block = (128-node tile, 20-col group). gt[b][c][j] = E_j * y[j][c];
// c==64 -> E_j; c>64 -> 0.
__global__ __launch_bounds__(256) void transform_kernel() {
    __shared__ __align__(16) float yt[20][132];
    __shared__ float es[128];
    const int tid = threadIdx.x;
    const int base = blockIdx.x * 128;
    const int cg   = blockIdx.y;               // 0..3
    const int b    = base >> 12;
    const int jb   = base & (NNODE - 1);

    for (int idx = tid; idx < 640; idx += 256) {
        int r = idx / 5, q = idx - r * 5;
        float4 v = *(const float4*)(d_y + (long)(base + r) * NP + cg * 20 + q * 4);
        yt[q * 4 + 0][r] = v.x;
        yt[q * 4 + 1][r] = v.y;
        yt[q * 4 + 2][r] = v.z;
        yt[q * 4 + 3][r] = v.w;
    }
    if (tid < 32) {
        float4 e4 = ((const float4*)(d_E + base))[tid];
        es[tid * 4 + 0] = e4.x; es[tid * 4 + 1] = e4.y;
        es[tid * 4 + 2] = e4.z; es[tid * 4 + 3] = e4.w;
    }
    __syncthreads();
    for (int idx = tid; idx < 640; idx += 256) {
        int c = idx >> 5, jq = idx & 31;
        int j0 = jq * 4, gc = cg * 20 + c;
        float4 yv = *(const float4*)(&yt[c][j0]);
        float4 o;
        if (gc < 64) {
            o.x = es[j0 + 0] * yv.x; o.y = es[j0 + 1] * yv.y;
            o.z = es[j0 + 2] * yv.z; o.w = es[j0 + 3] * yv.w;
        } else if (gc == 64) {
            o.x = es[j0]; o.y = es[j0 + 1]; o.z = es[j0 + 2]; o.w = es[j0 + 3];
        } else {
            o.x = o.y = o.z = o.w = 0.f;
        }
        *(float4*)(d_gt + ((long)b * NP + gc) * NNODE + jb + j0) = o;
    }
}

// --------------------------- fp16 mma GEMM ---------------------------------
// MODE 0: y[16384x80] = features[16384x256] @ Mred^T + bias     (KT=8)
// MODE 1: out = (adj @ gt^T) / (N*Z), Z fused from column 64     (KT=128)
// Staging: LDG.128 fp32 -> cvt f16x2 -> STS.64, 2-tile reg prefetch,
// double-buffered smem; fragments via ldmatrix.x4.
template<int MODE>
__global__ __launch_bounds__(256, 1)
void gemm_kernel(const float* __restrict__ Abase, float* __restrict__ OutP)
{
    constexpr int lda = MODE ? NNODE : DD;
    constexpr int ldb = MODE ? NNODE : DD;
    constexpr int KT  = MODE ? NNODE / BK : DD / BK;

    __shared__ __align__(16) char smA[2][BM * SA];
    __shared__ __align__(16) char smB[2][NP * SB];
    __shared__ float Zs[BM];

    const int mtile = blockIdx.x, batch = blockIdx.y;
    const int tid = threadIdx.x;
    const int wid = tid >> 5, lane = tid & 31;
    const int wm = wid & 3, wn = wid >> 2;
    const int g = lane >> 2, t = lane & 3;
    const int ra = tid >> 3;            // staging row 0..31
    const int ca8 = (tid & 7) * 8;      // staging byte col

    const float* A = Abase + (MODE ? (long)batch * NNODE * NNODE : 0L)
                           + (long)mtile * BM * lda;
    const float* Bg = MODE ? (d_gt + (long)batch * NP * NNODE) : d_Mred;
    const float* Ab = A + (long)ra * lda + (tid & 7) * 4;
    const float* Bb = Bg + (long)ra * ldb + (tid & 7) * 4;

    float4 pa[2][4];                    // [slot][row-group]
    float4 pb[2][3];

    float acc[2][5][4] = {};

    auto ldtile = [&](int kt, int P) {
        const float* ap = Ab + (long)kt * BK;
        pa[P][0] = *(const float4*)(ap);
        pa[P][1] = *(const float4*)(ap + 32L * lda);
        pa[P][2] = *(const float4*)(ap + 64L * lda);
        pa[P][3] = *(const float4*)(ap + 96L * lda);
        const float* bp = Bb + (long)kt * BK;
        pb[P][0] = *(const float4*)(bp);
        pb[P][1] = *(const float4*)(bp + 32L * ldb);
        if (tid < 128) pb[P][2] = *(const float4*)(bp + 64L * ldb);
    };

    auto sttile = [&](int P, int S) {
        char* da = smA[S] + ra * SA + ca8;
        #pragma unroll
        for (int q = 0; q < 4; q++)
            *(uint2*)(da + q * 32 * SA) =
                make_uint2(pack2(pa[P][q].x, pa[P][q].y),
                           pack2(pa[P][q].z, pa[P][q].w));
        char* db = smB[S] + ra * SB + ca8;
        #pragma unroll
        for (int q = 0; q < 2; q++)
            *(uint2*)(db + q * 32 * SB) =
                make_uint2(pack2(pb[P][q].x, pb[P][q].y),
                           pack2(pb[P][q].z, pb[P][q].w));
        if (tid < 128)
            *(uint2*)(db + 64 * SB) =
                make_uint2(pack2(pb[P][2].x, pb[P][2].y),
                           pack2(pb[P][2].z, pb[P][2].w));
    };

    auto compute = [&](const char* sA, const char* sB) {
        unsigned af[2][2][4], bf[5][4];
        unsigned a0 = su32(sA + (wm * 32 + (lane & 15)) * SA + ((lane & 16) >> 1) * 2);
        unsigned b0 = su32(sB + (wn * 40 + (lane & 7)) * SB + (lane >> 3) * 16);
        #pragma unroll
        for (int i = 0; i < 2; i++)
            #pragma unroll
            for (int kh = 0; kh < 2; kh++)
                ldsm4(af[i][kh], a0 + i * 16 * SA + kh * 32);
        #pragma unroll
        for (int j = 0; j < 5; j++)
            ldsm4(bf[j], b0 + j * 8 * SB);
        #pragma unroll
        for (int kh = 0; kh < 2; kh++)
            #pragma unroll
            for (int i = 0; i < 2; i++)
                #pragma unroll
                for (int j = 0; j < 5; j++)
                    mma16(acc[i][j], af[i][kh], bf[j] + kh * 2);
    };

    ldtile(0, 0);
    ldtile(1, 1);
    sttile(0, 0);
    __syncthreads();

    for (int k2 = 0; k2 < KT; k2 += 2) {
        if (k2 + 2 < KT) ldtile(k2 + 2, 0);
        sttile(1, 1);                       // tile k2+1 (KT even)
        compute(smA[0], smB[0]);            // tile k2
        __syncthreads();
        if (k2 + 3 < KT) ldtile(k2 + 3, 1);
        if (k2 + 2 < KT) sttile(0, 0);
        compute(smA[1], smB[1]);            // tile k2+1
        __syncthreads();
    }

    if (MODE == 0) {
        #pragma unroll
        for (int i = 0; i < 2; i++) {
            long r0 = (long)mtile * BM + wm * 32 + i * 16 + g, r1 = r0 + 8;
            #pragma unroll
            for (int j = 0; j < 5; j++) {
                int colb = wn * 40 + j * 8 + 2 * t;
                if (colb < 64) {
                    float b0 = d_biasv[colb], b1 = d_biasv[colb + 1];
                    *(float2*)(d_y + r0 * NP + colb) =
                        make_float2(acc[i][j][0] + b0, acc[i][j][1] + b1);
                    *(float2*)(d_y + r1 * NP + colb) =
                        make_float2(acc[i][j][2] + b0, acc[i][j][3] + b1);
                } else if (colb == 64) {
                    float b0 = d_biasv[64];
                    d_y[r0 * NP + 64] = acc[i][j][0] + b0;
                    d_y[r1 * NP + 64] = acc[i][j][2] + b0;
                }
            }
        }
    } else {
        if (wn == 1 && t == 0) {
            #pragma unroll
            for (int i = 0; i < 2; i++) {
                Zs[wm * 32 + i * 16 + g]     = acc[i][3][0];
                Zs[wm * 32 + i * 16 + g + 8] = acc[i][3][2];
            }
        }
        __syncthreads();
        #pragma unroll
        for (int i = 0; i < 2; i++) {
            int rl0 = wm * 32 + i * 16 + g;
            float rz0 = 1.0f / (4096.0f * Zs[rl0]);
            float rz1 = 1.0f / (4096.0f * Zs[rl0 + 8]);
            long ro0 = ((long)batch * NNODE + mtile * BM + rl0) * 64;
            long ro1 = ro0 + 8 * 64;
            #pragma unroll
            for (int j = 0; j < 5; j++) {
                int colb = wn * 40 + j * 8 + 2 * t;
                if (colb < 64) {
                    *(float2*)(OutP + ro0 + colb) =
                        make_float2(acc[i][j][0] * rz0, acc[i][j][1] * rz0);
                    *(float2*)(OutP + ro1 + colb) =
                        make_float2(acc[i][j][2] * rz1, acc[i][j][3] * rz1);
                }
            }
        }
    }
}

// ------------------------------ launch ------------------------------------
extern "C" void kernel_launch(void* const* d_in, const int* in_sizes, int n_in,
                              void* d_out, int out_size) {
    const float* features = (const float*)d_in[0];
    const float* adj      = (const float*)d_in[1];
    const float* W_fc     = (const float*)d_in[2];
    const float* b_fc     = (const float*)d_in[3];
    const float* W_attn   = (const float*)d_in[4];
    float* out = (float*)d_out;

    prep_kernel<<<1, 256>>>(W_fc, b_fc, W_attn);
    gemm_kernel<0><<<dim3(16384 / BM, 1), 256>>>(features, nullptr);
    srcmax_kernel<<<BATCH, 256>>>();
    e_kernel<<<16384 / 256, 256>>>();
    transform_kernel<<<dim3(16384 / 128, 4), 256>>>();
    gemm_kernel<1><<<dim3(NNODE / BM, BATCH), 256>>>(adj, out);
}

// round 6
// speedup vs baseline: 1.1075x; 1.1075x over previous
#include <cuda_runtime.h>
#include <cuda_fp16.h>
#include <cstdint>

// ---------------------------------------------------------------------------
// GAT layer, algebraically reduced:
//   alpha[i,j] = adj[i,j]*E[j] / sum_j adj[i,j]*E[j],  E = exp(src)  (no max
//   subtraction needed: |src| < ~1, and the ratio is shift-invariant)
//   out[b,i,:] = (adj @ (E*h_sum)) / (N * (adj @ E))
// adj fp32 {0,1} is converted to fp16 {0,1.875} with a single PRMT (top
// half-word of 1.0f is 0x3F80 = fp16 1.875); the uniform scale cancels in the
// numerator/Z ratio. g = E*h_sum is produced directly in fp16 by the
// projection kernel's epilogue (transform fused, 3 small kernels removed).
// ---------------------------------------------------------------------------

#define BATCH 4
#define NNODE 4096
#define DD    256
#define NP    80          // 64 h_sum cols + 1 E col + 15 zero pad
#define BM    128
#define BK    32
#define SA    80          // smem row stride bytes (64B fp16 data + 16B pad)
#define SB    80

__device__ float d_Mred[NP * DD];            // [c][d] (rows 65..79 zero)
__device__ float d_biasv[NP];
__device__ __align__(16) __half d_gh[BATCH * NP * NNODE];  // [b][c][j] fp16
__device__ float d_scratch;

// ------------------------------ helpers -----------------------------------
__device__ __forceinline__ unsigned su32(const void* p) {
    return (unsigned)__cvta_generic_to_shared(p);
}
__device__ __forceinline__ unsigned pack2(float lo, float hi) {
    unsigned d;
    asm("cvt.rn.f16x2.f32 %0, %1, %2;" : "=r"(d) : "f"(hi), "f"(lo));
    return d;
}
__device__ __forceinline__ void ldsm4(unsigned* r, unsigned a) {
    asm volatile("ldmatrix.sync.aligned.m8n8.x4.shared.b16 {%0,%1,%2,%3}, [%4];"
                 : "=r"(r[0]), "=r"(r[1]), "=r"(r[2]), "=r"(r[3]) : "r"(a));
}
__device__ __forceinline__ void mma16(float* d, const unsigned* a, const unsigned* b) {
    asm volatile("mma.sync.aligned.m16n8k16.row.col.f32.f16.f16.f32 "
                 "{%0,%1,%2,%3}, {%4,%5,%6,%7}, {%8,%9}, {%0,%1,%2,%3};"
                 : "+f"(d[0]), "+f"(d[1]), "+f"(d[2]), "+f"(d[3])
                 : "r"(a[0]), "r"(a[1]), "r"(a[2]), "r"(a[3]),
                   "r"(b[0]), "r"(b[1]));
}

// ------------------------------ prep --------------------------------------
__global__ void prep_kernel(const float* __restrict__ W_fc,
                            const float* __restrict__ b_fc,
                            const float* __restrict__ W_attn) {
    __shared__ float ws[256];
    const int tid = threadIdx.x;
    {
        int h = tid >> 6, o = tid & 63;
        ws[tid] = 0.25f * (W_attn[       h * 128 + o] +
                           W_attn[ 512 + h * 128 + o] +
                           W_attn[1024 + h * 128 + o] +
                           W_attn[1536 + h * 128 + o]);
    }
    __syncthreads();
    for (int idx = tid; idx < NP * DD; idx += 256) {
        int c = idx / DD, d = idx - c * DD;
        float v = 0.f;
        if (c < 64) {
            v = W_fc[c * DD + d] + W_fc[(64 + c) * DD + d] +
                W_fc[(128 + c) * DD + d] + W_fc[(192 + c) * DD + d];
        } else if (c == 64) {
            for (int r = 0; r < 256; r++) v += W_fc[r * DD + d] * ws[r];
        }
        d_Mred[idx] = v;
    }
    if (tid < NP) {
        float v = 0.f;
        if (tid < 64) {
            v = b_fc[tid] + b_fc[64 + tid] + b_fc[128 + tid] + b_fc[192 + tid];
        } else if (tid == 64) {
            for (int r = 0; r < 256; r++) v += b_fc[r] * ws[r];
        }
        d_biasv[tid] = v;
    }
}

// ---------------- projection + fused transform (writes g fp16) -------------
// y[16384x80] = features[16384x256] @ Mred^T + bias; then per row j:
// E = exp(y[j,64]); d_gh[b][c][j] = fp16(E*y[j,c]) (c<64), fp16(E) (c==64).
__global__ __launch_bounds__(256, 1)
void proj_kernel(const float* __restrict__ Abase)
{
    constexpr int lda = DD, ldb = DD, KT = DD / BK;

    __shared__ __align__(16) char smA[2][BM * SA];
    __shared__ __align__(16) char smB[2][NP * SB];
    __shared__ float Zs[BM];

    const int mtile = blockIdx.x;
    const int tid = threadIdx.x;
    const int wid = tid >> 5, lane = tid & 31;
    const int wm = wid & 3, wn = wid >> 2;
    const int g = lane >> 2, t = lane & 3;
    const int ra = tid >> 3;
    const int ca8 = (tid & 7) * 8;

    const float* A = Abase + (long)mtile * BM * lda;
    const float* Ab = A + (long)ra * lda + (tid & 7) * 4;
    const float* Bb = d_Mred + (long)ra * ldb + (tid & 7) * 4;

    float4 pa[2][4];
    float4 pb[2][3];
    float acc[2][5][4] = {};

    auto ldtile = [&](int kt, int P) {
        const float* ap = Ab + (long)kt * BK;
        pa[P][0] = *(const float4*)(ap);
        pa[P][1] = *(const float4*)(ap + 32L * lda);
        pa[P][2] = *(const float4*)(ap + 64L * lda);
        pa[P][3] = *(const float4*)(ap + 96L * lda);
        const float* bp = Bb + (long)kt * BK;
        pb[P][0] = *(const float4*)(bp);
        pb[P][1] = *(const float4*)(bp + 32L * ldb);
        if (tid < 128) pb[P][2] = *(const float4*)(bp + 64L * ldb);
    };
    auto sttile = [&](int P, int S) {
        char* da = smA[S] + ra * SA + ca8;
        #pragma unroll
        for (int q = 0; q < 4; q++)
            *(uint2*)(da + q * 32 * SA) =
                make_uint2(pack2(pa[P][q].x, pa[P][q].y),
                           pack2(pa[P][q].z, pa[P][q].w));
        char* db = smB[S] + ra * SB + ca8;
        #pragma unroll
        for (int q = 0; q < 2; q++)
            *(uint2*)(db + q * 32 * SB) =
                make_uint2(pack2(pb[P][q].x, pb[P][q].y),
                           pack2(pb[P][q].z, pb[P][q].w));
        if (tid < 128)
            *(uint2*)(db + 64 * SB) =
                make_uint2(pack2(pb[P][2].x, pb[P][2].y),
                           pack2(pb[P][2].z, pb[P][2].w));
    };
    auto compute = [&](const char* sA, const char* sB) {
        unsigned af[2][2][4], bf[5][4];
        unsigned a0 = su32(sA + (wm * 32 + (lane & 15)) * SA + ((lane & 16) >> 1) * 2);
        unsigned b0 = su32(sB + (wn * 40 + (lane & 7)) * SB + (lane >> 3) * 16);
        #pragma unroll
        for (int i = 0; i < 2; i++)
            #pragma unroll
            for (int kh = 0; kh < 2; kh++)
                ldsm4(af[i][kh], a0 + i * 16 * SA + kh * 32);
        #pragma unroll
        for (int j = 0; j < 5; j++)
            ldsm4(bf[j], b0 + j * 8 * SB);
        #pragma unroll
        for (int kh = 0; kh < 2; kh++)
            #pragma unroll
            for (int i = 0; i < 2; i++)
                #pragma unroll
                for (int j = 0; j < 5; j++)
                    mma16(acc[i][j], af[i][kh], bf[j] + kh * 2);
    };

    ldtile(0, 0);
    ldtile(1, 1);
    sttile(0, 0);
    __syncthreads();
    for (int k2 = 0; k2 < KT; k2 += 2) {
        if (k2 + 2 < KT) ldtile(k2 + 2, 0);
        sttile(1, 1);
        compute(smA[0], smB[0]);
        __syncthreads();
        if (k2 + 3 < KT) ldtile(k2 + 3, 1);
        if (k2 + 2 < KT) sttile(0, 0);
        compute(smA[1], smB[1]);
        __syncthreads();
    }

    // ---- fused transform epilogue: exchange src (col 64), write g fp16 ----
    const float b64 = d_biasv[64];
    if (wn == 1 && t == 0) {
        #pragma unroll
        for (int i = 0; i < 2; i++) {
            Zs[wm * 32 + i * 16 + g]     = acc[i][3][0] + b64;
            Zs[wm * 32 + i * 16 + g + 8] = acc[i][3][2] + b64;
        }
    }
    __syncthreads();
    const int bb = (mtile * BM) >> 12;
    const int jbase = (mtile * BM) & (NNODE - 1);
    __half* gb = d_gh + (long)bb * NP * NNODE;
    #pragma unroll
    for (int i = 0; i < 2; i++) {
        int rl0 = wm * 32 + i * 16 + g;
        float E0 = __expf(Zs[rl0]);
        float E1 = __expf(Zs[rl0 + 8]);
        int j0 = jbase + rl0, j1 = j0 + 8;
        #pragma unroll
        for (int j = 0; j < 5; j++) {
            int colb = wn * 40 + j * 8 + 2 * t;
            if (colb < 64) {
                float c0 = d_biasv[colb], c1 = d_biasv[colb + 1];
                gb[(long)colb * NNODE + j0]       = __float2half(E0 * (acc[i][j][0] + c0));
                gb[(long)(colb + 1) * NNODE + j0] = __float2half(E0 * (acc[i][j][1] + c1));
                gb[(long)colb * NNODE + j1]       = __float2half(E1 * (acc[i][j][2] + c0));
                gb[(long)(colb + 1) * NNODE + j1] = __float2half(E1 * (acc[i][j][3] + c1));
            } else if (colb == 64) {
                gb[64L * NNODE + j0] = __float2half(E0);
                gb[64L * NNODE + j1] = __float2half(E1);
            }
        }
    }
}

// ---------------- L2 warm of g (keeps agg's B operand resident) ------------
__global__ void warm_kernel() {
    const uint4* p = (const uint4*)d_gh;
    float s = 0.f;
    for (long k = blockIdx.x * 256L + threadIdx.x; k < (long)BATCH * NP * NNODE / 8;
         k += gridDim.x * 256L) {
        uint4 v = p[k];
        s += __uint_as_float(v.x) + __uint_as_float(v.w);
    }
    if (s == 1.2345e-30f) d_scratch = s;   // never true; defeats DCE
}

// --------------------------- aggregation GEMM ------------------------------
// out = (adj @ g^T) / (N*Z), Z fused from column 64.
// A: adj fp32 -> PRMT -> fp16*1.875 (scale cancels). B: d_gh fp16 direct.
__global__ __launch_bounds__(256, 1)
void agg_kernel(const float* __restrict__ Abase, float* __restrict__ OutP)
{
    constexpr int lda = NNODE;           // floats
    constexpr int ldbh = NNODE;          // halves
    constexpr int KT = NNODE / BK;       // 128

    __shared__ __align__(16) char smA[2][BM * SA];
    __shared__ __align__(16) char smB[2][NP * SB];
    __shared__ float Zs[BM];

    const int mtile = blockIdx.x, batch = blockIdx.y;
    const int tid = threadIdx.x;
    const int wid = tid >> 5, lane = tid & 31;
    const int wm = wid & 3, wn = wid >> 2;
    const int g = lane >> 2, t = lane & 3;
    const int ra = tid >> 3;
    const int ca8 = (tid & 7) * 8;

    const float* A = Abase + (long)batch * NNODE * NNODE + (long)mtile * BM * lda;
    const float* Ab = A + (long)ra * lda + (tid & 7) * 4;
    const __half* Bh = d_gh + (long)batch * NP * NNODE;
    // B staging: threads 0..159 own two uint4 chunks (8 halves) each
    const int bi0 = tid, bi1 = tid + 160;                 // idx in [0,320)
    const __half* Bb0 = Bh + (long)(bi0 >> 2) * ldbh + (bi0 & 3) * 8;
    const __half* Bb1 = Bh + (long)(bi1 >> 2) * ldbh + (bi1 & 3) * 8;

    float4 pa[2][4];
    uint4 pbv[2][2];
    float acc[2][5][4] = {};

    auto ldtile = [&](int kt, int P) {
        const float* ap = Ab + (long)kt * BK;
        pa[P][0] = *(const float4*)(ap);
        pa[P][1] = *(const float4*)(ap + 32L * lda);
        pa[P][2] = *(const float4*)(ap + 64L * lda);
        pa[P][3] = *(const float4*)(ap + 96L * lda);
        if (tid < 160) {
            pbv[P][0] = *(const uint4*)(Bb0 + (long)kt * BK);
            pbv[P][1] = *(const uint4*)(Bb1 + (long)kt * BK);
        }
    };
    auto sttile = [&](int P, int S) {
        char* da = smA[S] + ra * SA + ca8;
        #pragma unroll
        for (int q = 0; q < 4; q++) {
            unsigned lo = __byte_perm(__float_as_uint(pa[P][q].x),
                                      __float_as_uint(pa[P][q].y), 0x7632);
            unsigned hi = __byte_perm(__float_as_uint(pa[P][q].z),
                                      __float_as_uint(pa[P][q].w), 0x7632);
            *(uint2*)(da + q * 32 * SA) = make_uint2(lo, hi);
        }
        if (tid < 160) {
            *(uint4*)(smB[S] + (bi0 >> 2) * SB + (bi0 & 3) * 16) = pbv[P][0];
            *(uint4*)(smB[S] + (bi1 >> 2) * SB + (bi1 & 3) * 16) = pbv[P][1];
        }
    };
    auto compute = [&](const char* sA, const char* sB) {
        unsigned af[2][2][4], bf[5][4];
        unsigned a0 = su32(sA + (wm * 32 + (lane & 15)) * SA + ((lane & 16) >> 1) * 2);
        unsigned b0 = su32(sB + (wn * 40 + (lane & 7)) * SB + (lane >> 3) * 16);
        #pragma unroll
        for (int i = 0; i < 2; i++)
            #pragma unroll
            for (int kh = 0; kh < 2; kh++)
                ldsm4(af[i][kh], a0 + i * 16 * SA + kh * 32);
        #pragma unroll
        for (int j = 0; j < 5; j++)
            ldsm4(bf[j], b0 + j * 8 * SB);
        #pragma unroll
        for (int kh = 0; kh < 2; kh++)
            #pragma unroll
            for (int i = 0; i < 2; i++)
                #pragma unroll
                for (int j = 0; j < 5; j++)
                    mma16(acc[i][j], af[i][kh], bf[j] + kh * 2);
    };

    ldtile(0, 0);
    ldtile(1, 1);
    sttile(0, 0);
    __syncthreads();
    for (int k2 = 0; k2 < KT; k2 += 2) {
        if (k2 + 2 < KT) ldtile(k2 + 2, 0);
        sttile(1, 1);
        compute(smA[0], smB[0]);
        __syncthreads();
        if (k2 + 3 < KT) ldtile(k2 + 3, 1);
        if (k2 + 2 < KT) sttile(0, 0);
        compute(smA[1], smB[1]);
        __syncthreads();
    }

    // ---- epilogue: normalize by Z (col 64); the 1.875 adj scale cancels ----
    if (wn == 1 && t == 0) {
        #pragma unroll
        for (int i = 0; i < 2; i++) {
            Zs[wm * 32 + i * 16 + g]     = acc[i][3][0];
            Zs[wm * 32 + i * 16 + g + 8] = acc[i][3][2];
        }
    }
    __syncthreads();
    #pragma unroll
    for (int i = 0; i < 2; i++) {
        int rl0 = wm * 32 + i * 16 + g;
        float rz0 = 1.0f / (4096.0f * Zs[rl0]);
        float rz1 = 1.0f / (4096.0f * Zs[rl0 + 8]);
        long ro0 = ((long)batch * NNODE + mtile * BM + rl0) * 64;
        long ro1 = ro0 + 8 * 64;
        #pragma unroll
        for (int j = 0; j < 5; j++) {
            int colb = wn * 40 + j * 8 + 2 * t;
            if (colb < 64) {
                *(float2*)(OutP + ro0 + colb) =
                    make_float2(acc[i][j][0] * rz0, acc[i][j][1] * rz0);
                *(float2*)(OutP + ro1 + colb) =
                    make_float2(acc[i][j][2] * rz1, acc[i][j][3] * rz1);
            }
        }
    }
}

// ------------------------------ launch ------------------------------------
extern "C" void kernel_launch(void* const* d_in, const int* in_sizes, int n_in,
                              void* d_out, int out_size) {
    const float* features = (const float*)d_in[0];
    const float* adj      = (const float*)d_in[1];
    const float* W_fc     = (const float*)d_in[2];
    const float* b_fc     = (const float*)d_in[3];
    const float* W_attn   = (const float*)d_in[4];
    float* out = (float*)d_out;

    prep_kernel<<<1, 256>>>(W_fc, b_fc, W_attn);
    proj_kernel<<<16384 / BM, 256>>>(features);
    warm_kernel<<<160, 256>>>();
    agg_kernel<<<dim3(NNODE / BM, BATCH), 256>>>(adj, out);
}

// round 7
// speedup vs baseline: 1.4428x; 1.3027x over previous
#include <cuda_runtime.h>
#include <cuda_fp16.h>
#include <cstdint>

// ---------------------------------------------------------------------------
// GAT layer, algebraically reduced:
//   alpha[i,j] = adj[i,j]*E[j] / sum_j adj[i,j]*E[j],  E = exp(src)
//   out[b,i,:] = (adj @ (E*h_sum)) / (N * (adj @ E))
// Unified cp.async-pipelined fp16 mma.sync GEMM (4 stages):
//   A fp32 staged raw via cp.async, converted to fp16 fragments on the
//   consumer side (LDS.64 + cvt.rn.f16x2) -- no blocking register prefetch.
//   B fp16 (Mred pre-halved; g written fp16 by the projection epilogue).
// ---------------------------------------------------------------------------

#define BATCH 4
#define NNODE 4096
#define DD    256
#define NP    80            // 64 h_sum cols + 1 E col + 15 pad
#define BM    128
#define BK    32
#define STAGES 4
#define SWA   40            // A smem row stride (words); banks conflict-free
#define SBB   80            // B smem row stride (bytes)
#define A_STG (BM * SWA * 4)          // 20480 B
#define B_STG (NP * SBB)              // 6400 B
#define OFF_B (STAGES * A_STG)        // 81920
#define OFF_Z (OFF_B + STAGES * B_STG)
#define SMEM_TOTAL (OFF_Z + 512)      // 108544 B

__device__ float  d_biasv[NP];
__device__ __align__(16) __half d_Mredh[NP * DD];          // [c][d] fp16
__device__ __align__(16) __half d_gh[BATCH * NP * NNODE];  // [b][c][j] fp16

// ------------------------------ helpers -----------------------------------
__device__ __forceinline__ unsigned su32(const void* p) {
    return (unsigned)__cvta_generic_to_shared(p);
}
__device__ __forceinline__ void cpa16(unsigned d, const void* s) {
    asm volatile("cp.async.cg.shared.global [%0], [%1], 16;\n" :: "r"(d), "l"(s));
}
__device__ __forceinline__ void cpcommit() {
    asm volatile("cp.async.commit_group;\n" ::);
}
template<int W> __device__ __forceinline__ void cpwait() {
    asm volatile("cp.async.wait_group %0;\n" :: "n"(W));
}
__device__ __forceinline__ unsigned pack2(float lo, float hi) {
    unsigned d;
    asm("cvt.rn.f16x2.f32 %0, %1, %2;" : "=r"(d) : "f"(hi), "f"(lo));
    return d;
}
__device__ __forceinline__ void ldsm4(unsigned* r, unsigned a) {
    asm volatile("ldmatrix.sync.aligned.m8n8.x4.shared.b16 {%0,%1,%2,%3}, [%4];"
                 : "=r"(r[0]), "=r"(r[1]), "=r"(r[2]), "=r"(r[3]) : "r"(a));
}
__device__ __forceinline__ void mma16(float* d, const unsigned* a, const unsigned* b) {
    asm volatile("mma.sync.aligned.m16n8k16.row.col.f32.f16.f16.f32 "
                 "{%0,%1,%2,%3}, {%4,%5,%6,%7}, {%8,%9}, {%0,%1,%2,%3};"
                 : "+f"(d[0]), "+f"(d[1]), "+f"(d[2]), "+f"(d[3])
                 : "r"(a[0]), "r"(a[1]), "r"(a[2]), "r"(a[3]),
                   "r"(b[0]), "r"(b[1]));
}

// ------------------------------ prep --------------------------------------
__global__ void prep_kernel(const float* __restrict__ W_fc,
                            const float* __restrict__ b_fc,
                            const float* __restrict__ W_attn) {
    __shared__ float ws[256];
    const int tid = threadIdx.x;
    {
        int h = tid >> 6, o = tid & 63;
        ws[tid] = 0.25f * (W_attn[       h * 128 + o] +
                           W_attn[ 512 + h * 128 + o] +
                           W_attn[1024 + h * 128 + o] +
                           W_attn[1536 + h * 128 + o]);
    }
    __syncthreads();
    for (int idx = tid; idx < NP * DD; idx += 256) {
        int c = idx / DD, d = idx - c * DD;
        float v = 0.f;
        if (c < 64) {
            v = W_fc[c * DD + d] + W_fc[(64 + c) * DD + d] +
                W_fc[(128 + c) * DD + d] + W_fc[(192 + c) * DD + d];
        } else if (c == 64) {
            for (int r = 0; r < 256; r++) v += W_fc[r * DD + d] * ws[r];
        }
        d_Mredh[idx] = __float2half(v);
    }
    if (tid < NP) {
        float v = 0.f;
        if (tid < 64) {
            v = b_fc[tid] + b_fc[64 + tid] + b_fc[128 + tid] + b_fc[192 + tid];
        } else if (tid == 64) {
            for (int r = 0; r < 256; r++) v += b_fc[r] * ws[r];
        }
        d_biasv[tid] = v;
    }
}

// --------------------- unified pipelined fp16 GEMM -------------------------
// MODE 0: proj: acc = features[16384x256] @ Mredh^T; epilogue adds bias,
//         computes E=exp(col64) and writes g fp16 to d_gh (transform fused).
// MODE 1: agg:  acc = adj[4096x4096] @ gh^T; epilogue normalizes by col 64.
template<int MODE>
__global__ __launch_bounds__(256, 1)
void gemm_kernel(const float* __restrict__ Abase, float* __restrict__ OutP)
{
    constexpr int lda = MODE ? NNODE : DD;     // floats
    constexpr int ldb = MODE ? NNODE : DD;     // halves
    constexpr int KT  = MODE ? NNODE / BK : DD / BK;

    extern __shared__ __align__(16) char sm[];
    float* Zs = (float*)(sm + OFF_Z);

    const int mtile = blockIdx.x, batch = blockIdx.y;
    const int tid = threadIdx.x;
    const int wid = tid >> 5, lane = tid & 31;
    const int wm = wid & 3, wn = wid >> 2;
    const int g = lane >> 2, t = lane & 3;

    const float* A = Abase + (MODE ? (long)batch * NNODE * NNODE : 0L)
                           + (long)mtile * BM * lda;
    const __half* Bh = MODE ? (d_gh + (long)batch * NP * NNODE) : d_Mredh;

    const int ar = tid >> 3, ac = tid & 7;         // A chunk coords
    const int br = tid >> 2, bc = tid & 3;         // B chunk coords

    auto issue = [&](int s, int kt) {
        char* as = sm + s * A_STG;
        const float* ag = A + (long)kt * BK;
        #pragma unroll
        for (int q = 0; q < 4; q++) {
            int r = q * 32 + ar;
            cpa16(su32(as + r * (SWA * 4) + ac * 16), ag + (long)r * lda + ac * 4);
        }
        char* bs = sm + OFF_B + s * B_STG;
        const __half* bg = Bh + (long)kt * BK;
        cpa16(su32(bs + br * SBB + bc * 16), bg + (long)br * ldb + bc * 8);
        if (tid < 64) {
            int r2 = 64 + br;
            cpa16(su32(bs + r2 * SBB + bc * 16), bg + (long)r2 * ldb + bc * 8);
        }
    };

    float acc[2][5][4] = {};

    auto compute = [&](int s) {
        const float* as = (const float*)(sm + s * A_STG);
        const char*  bs = sm + OFF_B + s * B_STG;
        unsigned af[2][2][4], bf[5][4];
        unsigned b0 = su32(bs + (wn * 40 + (lane & 7)) * SBB + (lane >> 3) * 16);
        #pragma unroll
        for (int j = 0; j < 5; j++) ldsm4(bf[j], b0 + j * 8 * SBB);
        #pragma unroll
        for (int i = 0; i < 2; i++) {
            const float* pr = as + (wm * 32 + i * 16 + g) * SWA + 2 * t;
            #pragma unroll
            for (int kh = 0; kh < 2; kh++) {
                const float* p = pr + kh * 16;
                float2 v0 = *(const float2*)(p);
                float2 v1 = *(const float2*)(p + 8 * SWA);
                float2 v2 = *(const float2*)(p + 8);
                float2 v3 = *(const float2*)(p + 8 * SWA + 8);
                af[i][kh][0] = pack2(v0.x, v0.y);
                af[i][kh][1] = pack2(v1.x, v1.y);
                af[i][kh][2] = pack2(v2.x, v2.y);
                af[i][kh][3] = pack2(v3.x, v3.y);
            }
        }
        #pragma unroll
        for (int kh = 0; kh < 2; kh++)
            #pragma unroll
            for (int i = 0; i < 2; i++)
                #pragma unroll
                for (int j = 0; j < 5; j++)
                    mma16(acc[i][j], af[i][kh], bf[j] + kh * 2);
    };

    #pragma unroll
    for (int s = 0; s < STAGES - 1; s++) { issue(s, s); cpcommit(); }

    for (int k = 0; k < KT; k++) {
        cpwait<STAGES - 2>();
        __syncthreads();
        if (k + STAGES - 1 < KT) issue((k + STAGES - 1) % STAGES, k + STAGES - 1);
        cpcommit();
        compute(k % STAGES);
    }

    // ------------------------------ epilogues ------------------------------
    if (MODE == 0) {
        const float b64 = d_biasv[64];
        if (wn == 1 && t == 0) {
            #pragma unroll
            for (int i = 0; i < 2; i++) {
                Zs[wm * 32 + i * 16 + g]     = acc[i][3][0] + b64;
                Zs[wm * 32 + i * 16 + g + 8] = acc[i][3][2] + b64;
            }
        }
        __syncthreads();
        const int bb = (mtile * BM) >> 12;
        const int jbase = (mtile * BM) & (NNODE - 1);
        __half* gb = d_gh + (long)bb * NP * NNODE;
        #pragma unroll
        for (int i = 0; i < 2; i++) {
            int rl0 = wm * 32 + i * 16 + g;
            float E0 = __expf(Zs[rl0]);
            float E1 = __expf(Zs[rl0 + 8]);
            int j0 = jbase + rl0, j1 = j0 + 8;
            #pragma unroll
            for (int j = 0; j < 5; j++) {
                int colb = wn * 40 + j * 8 + 2 * t;
                if (colb < 64) {
                    float c0 = d_biasv[colb], c1 = d_biasv[colb + 1];
                    gb[(long)colb * NNODE + j0]       = __float2half(E0 * (acc[i][j][0] + c0));
                    gb[(long)(colb + 1) * NNODE + j0] = __float2half(E0 * (acc[i][j][1] + c1));
                    gb[(long)colb * NNODE + j1]       = __float2half(E1 * (acc[i][j][2] + c0));
                    gb[(long)(colb + 1) * NNODE + j1] = __float2half(E1 * (acc[i][j][3] + c1));
                } else if (colb == 64) {
                    gb[64L * NNODE + j0] = __float2half(E0);
                    gb[64L * NNODE + j1] = __float2half(E1);
                }
            }
        }
    } else {
        if (wn == 1 && t == 0) {
            #pragma unroll
            for (int i = 0; i < 2; i++) {
                Zs[wm * 32 + i * 16 + g]     = acc[i][3][0];
                Zs[wm * 32 + i * 16 + g + 8] = acc[i][3][2];
            }
        }
        __syncthreads();
        #pragma unroll
        for (int i = 0; i < 2; i++) {
            int rl0 = wm * 32 + i * 16 + g;
            float rz0 = 1.0f / (4096.0f * Zs[rl0]);
            float rz1 = 1.0f / (4096.0f * Zs[rl0 + 8]);
            long ro0 = ((long)batch * NNODE + mtile * BM + rl0) * 64;
            long ro1 = ro0 + 8 * 64;
            #pragma unroll
            for (int j = 0; j < 5; j++) {
                int colb = wn * 40 + j * 8 + 2 * t;
                if (colb < 64) {
                    *(float2*)(OutP + ro0 + colb) =
                        make_float2(acc[i][j][0] * rz0, acc[i][j][1] * rz0);
                    *(float2*)(OutP + ro1 + colb) =
                        make_float2(acc[i][j][2] * rz1, acc[i][j][3] * rz1);
                }
            }
        }
    }
}

// ------------------------------ launch ------------------------------------
extern "C" void kernel_launch(void* const* d_in, const int* in_sizes, int n_in,
                              void* d_out, int out_size) {
    const float* features = (const float*)d_in[0];
    const float* adj      = (const float*)d_in[1];
    const float* W_fc     = (const float*)d_in[2];
    const float* b_fc     = (const float*)d_in[3];
    const float* W_attn   = (const float*)d_in[4];
    float* out = (float*)d_out;

    cudaFuncSetAttribute(gemm_kernel<0>,
                         cudaFuncAttributeMaxDynamicSharedMemorySize, SMEM_TOTAL);
    cudaFuncSetAttribute(gemm_kernel<1>,
                         cudaFuncAttributeMaxDynamicSharedMemorySize, SMEM_TOTAL);

    prep_kernel<<<1, 256>>>(W_fc, b_fc, W_attn);
    gemm_kernel<0><<<16384 / BM, 256, SMEM_TOTAL>>>(features, nullptr);
    gemm_kernel<1><<<dim3(NNODE / BM, BATCH), 256, SMEM_TOTAL>>>(adj, out);
}

// round 10
// speedup vs baseline: 1.9113x; 1.3247x over previous
#include <cuda_runtime.h>
#include <cuda_fp16.h>
#include <cstdint>

// ---------------------------------------------------------------------------
// GAT layer, algebraically reduced:
//   alpha[i,j] = adj[i,j]*E[j] / sum_j adj[i,j]*E[j],  E = exp(src)
//   out[b,i,:] = (adj @ (E*h_sum)) / (N * (adj @ E))
// Unified cp.async-pipelined fp16 mma.sync GEMM (6 stages):
//   A fp32 staged raw via cp.async, converted to fp16 fragments on the
//   consumer side (LDS.64 + cvt.rn.f16x2).
//   B fp16 (Mred pre-halved; g written fp16 by the projection epilogue).
// prep parallelized across 81 blocks (was single-block, 51 us -> ~3 us).
// (Resubmission of R8 source: previous round died to an infra failure,
//  "GB300 container failed twice" -- kernel never evaluated.)
// ---------------------------------------------------------------------------

#define BATCH 4
#define NNODE 4096
#define DD    256
#define NP    80            // 64 h_sum cols + 1 E col + 15 pad
#define BM    128
#define BK    32
#define STAGES 6
#define SWA   40            // A smem row stride (words); banks conflict-free
#define SBB   80            // B smem row stride (bytes)
#define A_STG (BM * SWA * 4)          // 20480 B
#define B_STG (NP * SBB)              // 6400 B
#define OFF_B (STAGES * A_STG)        // 122880
#define OFF_Z (OFF_B + STAGES * B_STG)
#define SMEM_TOTAL (OFF_Z + 512)      // 161792 B

__device__ float  d_biasv[NP];
__device__ __align__(16) __half d_Mredh[NP * DD];          // [c][d] fp16
__device__ __align__(16) __half d_gh[BATCH * NP * NNODE];  // [b][c][j] fp16

// ------------------------------ helpers -----------------------------------
__device__ __forceinline__ unsigned su32(const void* p) {
    return (unsigned)__cvta_generic_to_shared(p);
}
__device__ __forceinline__ void cpa16(unsigned d, const void* s) {
    asm volatile("cp.async.cg.shared.global [%0], [%1], 16;\n" :: "r"(d), "l"(s));
}
__device__ __forceinline__ void cpcommit() {
    asm volatile("cp.async.commit_group;\n" ::);
}
template<int W> __device__ __forceinline__ void cpwait() {
    asm volatile("cp.async.wait_group %0;\n" :: "n"(W));
}
__device__ __forceinline__ unsigned pack2(float lo, float hi) {
    unsigned d;
    asm("cvt.rn.f16x2.f32 %0, %1, %2;" : "=r"(d) : "f"(hi), "f"(lo));
    return d;
}
__device__ __forceinline__ void ldsm4(unsigned* r, unsigned a) {
    asm volatile("ldmatrix.sync.aligned.m8n8.x4.shared.b16 {%0,%1,%2,%3}, [%4];"
                 : "=r"(r[0]), "=r"(r[1]), "=r"(r[2]), "=r"(r[3]) : "r"(a));
}
__device__ __forceinline__ void mma16(float* d, const unsigned* a, const unsigned* b) {
    asm volatile("mma.sync.aligned.m16n8k16.row.col.f32.f16.f16.f32 "
                 "{%0,%1,%2,%3}, {%4,%5,%6,%7}, {%8,%9}, {%0,%1,%2,%3};"
                 : "+f"(d[0]), "+f"(d[1]), "+f"(d[2]), "+f"(d[3])
                 : "r"(a[0]), "r"(a[1]), "r"(a[2]), "r"(a[3]),
                   "r"(b[0]), "r"(b[1]));
}

// ------------------------------ prep (parallel) -----------------------------
// Block c in [0,79]: row c of Mredh (256 threads = 256 d's).
// Block 80: bias vector.
__global__ void prep_kernel(const float* __restrict__ W_fc,
                            const float* __restrict__ b_fc,
                            const float* __restrict__ W_attn) {
    __shared__ float ws[256];
    const int c = blockIdx.x;
    const int tid = threadIdx.x;
    {
        int h = tid >> 6, o = tid & 63;
        ws[tid] = 0.25f * (W_attn[       h * 128 + o] +
                           W_attn[ 512 + h * 128 + o] +
                           W_attn[1024 + h * 128 + o] +
                           W_attn[1536 + h * 128 + o]);
    }
    __syncthreads();
    if (c < 64) {
        float v = W_fc[c * DD + tid] + W_fc[(64 + c) * DD + tid] +
                  W_fc[(128 + c) * DD + tid] + W_fc[(192 + c) * DD + tid];
        d_Mredh[c * DD + tid] = __float2half(v);
    } else if (c == 64) {
        float v = 0.f;
        #pragma unroll 8
        for (int r = 0; r < 256; r++) v += W_fc[r * DD + tid] * ws[r];
        d_Mredh[64 * DD + tid] = __float2half(v);
    } else if (c < 80) {
        d_Mredh[c * DD + tid] = __float2half(0.f);
    } else {
        if (tid < 64) {
            d_biasv[tid] = b_fc[tid] + b_fc[64 + tid] +
                           b_fc[128 + tid] + b_fc[192 + tid];
        } else if (tid == 64) {
            float v = 0.f;
            for (int r = 0; r < 256; r++) v += b_fc[r] * ws[r];
            d_biasv[64] = v;
        } else if (tid < NP) {
            d_biasv[tid] = 0.f;
        }
    }
}

// --------------------- unified pipelined fp16 GEMM -------------------------
// MODE 0: proj: acc = features[16384x256] @ Mredh^T; epilogue adds bias,
//         computes E=exp(col64) and writes g fp16 to d_gh (transform fused).
// MODE 1: agg:  acc = adj[4096x4096] @ gh^T; epilogue normalizes by col 64.
template<int MODE>
__global__ __launch_bounds__(256, 1)
void gemm_kernel(const float* __restrict__ Abase, float* __restrict__ OutP)
{
    constexpr int lda = MODE ? NNODE : DD;     // floats
    constexpr int ldb = MODE ? NNODE : DD;     // halves
    constexpr int KT  = MODE ? NNODE / BK : DD / BK;

    extern __shared__ __align__(16) char sm[];
    float* Zs = (float*)(sm + OFF_Z);

    const int mtile = blockIdx.x, batch = blockIdx.y;
    const int tid = threadIdx.x;
    const int wid = tid >> 5, lane = tid & 31;
    const int wm = wid & 3, wn = wid >> 2;
    const int g = lane >> 2, t = lane & 3;

    const float* A = Abase + (MODE ? (long)batch * NNODE * NNODE : 0L)
                           + (long)mtile * BM * lda;
    const __half* Bh = MODE ? (d_gh + (long)batch * NP * NNODE) : d_Mredh;

    const int ar = tid >> 3, ac = tid & 7;         // A chunk coords
    const int br = tid >> 2, bc = tid & 3;         // B chunk coords

    auto issue = [&](int s, int kt) {
        char* as = sm + s * A_STG;
        const float* ag = A + (long)kt * BK;
        #pragma unroll
        for (int q = 0; q < 4; q++) {
            int r = q * 32 + ar;
            cpa16(su32(as + r * (SWA * 4) + ac * 16), ag + (long)r * lda + ac * 4);
        }
        char* bs = sm + OFF_B + s * B_STG;
        const __half* bg = Bh + (long)kt * BK;
        cpa16(su32(bs + br * SBB + bc * 16), bg + (long)br * ldb + bc * 8);
        if (tid < 64) {
            int r2 = 64 + br;
            cpa16(su32(bs + r2 * SBB + bc * 16), bg + (long)r2 * ldb + bc * 8);
        }
    };

    float acc[2][5][4] = {};

    auto compute = [&](int s) {
        const float* as = (const float*)(sm + s * A_STG);
        const char*  bs = sm + OFF_B + s * B_STG;
        unsigned af[2][2][4], bf[5][4];
        unsigned b0 = su32(bs + (wn * 40 + (lane & 7)) * SBB + (lane >> 3) * 16);
        #pragma unroll
        for (int j = 0; j < 5; j++) ldsm4(bf[j], b0 + j * 8 * SBB);
        #pragma unroll
        for (int i = 0; i < 2; i++) {
            const float* pr = as + (wm * 32 + i * 16 + g) * SWA + 2 * t;
            #pragma unroll
            for (int kh = 0; kh < 2; kh++) {
                const float* p = pr + kh * 16;
                float2 v0 = *(const float2*)(p);
                float2 v1 = *(const float2*)(p + 8 * SWA);
                float2 v2 = *(const float2*)(p + 8);
                float2 v3 = *(const float2*)(p + 8 * SWA + 8);
                af[i][kh][0] = pack2(v0.x, v0.y);
                af[i][kh][1] = pack2(v1.x, v1.y);
                af[i][kh][2] = pack2(v2.x, v2.y);
                af[i][kh][3] = pack2(v3.x, v3.y);
            }
        }
        #pragma unroll
        for (int kh = 0; kh < 2; kh++)
            #pragma unroll
            for (int i = 0; i < 2; i++)
                #pragma unroll
                for (int j = 0; j < 5; j++)
                    mma16(acc[i][j], af[i][kh], bf[j] + kh * 2);
    };

    #pragma unroll
    for (int s = 0; s < STAGES - 1; s++) { issue(s, s); cpcommit(); }

    for (int k = 0; k < KT; k++) {
        cpwait<STAGES - 2>();
        __syncthreads();
        if (k + STAGES - 1 < KT) issue((k + STAGES - 1) % STAGES, k + STAGES - 1);
        cpcommit();
        compute(k % STAGES);
    }

    // ------------------------------ epilogues ------------------------------
    if (MODE == 0) {
        const float b64 = d_biasv[64];
        if (wn == 1 && t == 0) {
            #pragma unroll
            for (int i = 0; i < 2; i++) {
                Zs[wm * 32 + i * 16 + g]     = acc[i][3][0] + b64;
                Zs[wm * 32 + i * 16 + g + 8] = acc[i][3][2] + b64;
            }
        }
        __syncthreads();
        const int bb = (mtile * BM) >> 12;
        const int jbase = (mtile * BM) & (NNODE - 1);
        __half* gb = d_gh + (long)bb * NP * NNODE;
        #pragma unroll
        for (int i = 0; i < 2; i++) {
            int rl0 = wm * 32 + i * 16 + g;
            float E0 = __expf(Zs[rl0]);
            float E1 = __expf(Zs[rl0 + 8]);
            int j0 = jbase + rl0, j1 = j0 + 8;
            #pragma unroll
            for (int j = 0; j < 5; j++) {
                int colb = wn * 40 + j * 8 + 2 * t;
                if (colb < 64) {
                    float c0 = d_biasv[colb], c1 = d_biasv[colb + 1];
                    gb[(long)colb * NNODE + j0]       = __float2half(E0 * (acc[i][j][0] + c0));
                    gb[(long)(colb + 1) * NNODE + j0] = __float2half(E0 * (acc[i][j][1] + c1));
                    gb[(long)colb * NNODE + j1]       = __float2half(E1 * (acc[i][j][2] + c0));
                    gb[(long)(colb + 1) * NNODE + j1] = __float2half(E1 * (acc[i][j][3] + c1));
                } else if (colb == 64) {
                    gb[64L * NNODE + j0] = __float2half(E0);
                    gb[64L * NNODE + j1] = __float2half(E1);
                }
            }
        }
    } else {
        if (wn == 1 && t == 0) {
            #pragma unroll
            for (int i = 0; i < 2; i++) {
                Zs[wm * 32 + i * 16 + g]     = acc[i][3][0];
                Zs[wm * 32 + i * 16 + g + 8] = acc[i][3][2];
            }
        }
        __syncthreads();
        #pragma unroll
        for (int i = 0; i < 2; i++) {
            int rl0 = wm * 32 + i * 16 + g;
            float rz0 = 1.0f / (4096.0f * Zs[rl0]);
            float rz1 = 1.0f / (4096.0f * Zs[rl0 + 8]);
            long ro0 = ((long)batch * NNODE + mtile * BM + rl0) * 64;
            long ro1 = ro0 + 8 * 64;
            #pragma unroll
            for (int j = 0; j < 5; j++) {
                int colb = wn * 40 + j * 8 + 2 * t;
                if (colb < 64) {
                    *(float2*)(OutP + ro0 + colb) =
                        make_float2(acc[i][j][0] * rz0, acc[i][j][1] * rz0);
                    *(float2*)(OutP + ro1 + colb) =
                        make_float2(acc[i][j][2] * rz1, acc[i][j][3] * rz1);
                }
            }
        }
    }
}

// ------------------------------ launch ------------------------------------
extern "C" void kernel_launch(void* const* d_in, const int* in_sizes, int n_in,
                              void* d_out, int out_size) {
    const float* features = (const float*)d_in[0];
    const float* adj      = (const float*)d_in[1];
    const float* W_fc     = (const float*)d_in[2];
    const float* b_fc     = (const float*)d_in[3];
    const float* W_attn   = (const float*)d_in[4];
    float* out = (float*)d_out;

    cudaFuncSetAttribute(gemm_kernel<0>,
                         cudaFuncAttributeMaxDynamicSharedMemorySize, SMEM_TOTAL);
    cudaFuncSetAttribute(gemm_kernel<1>,
                         cudaFuncAttributeMaxDynamicSharedMemorySize, SMEM_TOTAL);

    prep_kernel<<<81, 256>>>(W_fc, b_fc, W_attn);
    gemm_kernel<0><<<16384 / BM, 256, SMEM_TOTAL>>>(features, nullptr);
    gemm_kernel<1><<<dim3(NNODE / BM, BATCH), 256, SMEM_TOTAL>>>(adj, out);
}

// round 12
// speedup vs baseline: 2.1102x; 1.1041x over previous
#include <cuda_runtime.h>
#include <cuda_fp16.h>
#include <cstdint>

// ---------------------------------------------------------------------------
// GAT layer, algebraically reduced:
//   alpha[i,j] = adj[i,j]*E[j] / sum_j adj[i,j]*E[j],  E = exp(src)
//   out[b,i,:] = (adj @ (E*h_sum)) / (N * (adj @ E))
// cp.async-pipelined fp16 mma.sync GEMM, 512 threads (16 warps: 8m x 2n,
// warp tile m16 x n40), 4 stages. A fp32 staged raw, converted to fp16
// fragments consumer-side (LDS.64 + cvt.rn.f16x2). B fp16 in gmem.
// ---------------------------------------------------------------------------

#define BATCH 4
#define NNODE 4096
#define DD    256
#define NP    80            // 64 h_sum cols + 1 E col + 15 pad
#define BM    128
#define BK    32
#define STAGES 4
#define THREADS 512
#define SWA   40            // A smem row stride (words); banks conflict-free
#define SBB   80            // B smem row stride (bytes)
#define A_STG (BM * SWA * 4)          // 20480 B
#define B_STG (NP * SBB)              // 6400 B
#define OFF_B (STAGES * A_STG)        // 81920
#define OFF_Z (OFF_B + STAGES * B_STG)
#define SMEM_TOTAL (OFF_Z + 512)      // ~108 KB

__device__ float  d_biasv[NP];
__device__ __align__(16) __half d_Mredh[NP * DD];          // [c][d] fp16
__device__ __align__(16) __half d_gh[BATCH * NP * NNODE];  // [b][c][j] fp16

// ------------------------------ helpers -----------------------------------
__device__ __forceinline__ unsigned su32(const void* p) {
    return (unsigned)__cvta_generic_to_shared(p);
}
__device__ __forceinline__ void cpa16(unsigned d, const void* s) {
    asm volatile("cp.async.cg.shared.global [%0], [%1], 16;\n" :: "r"(d), "l"(s));
}
__device__ __forceinline__ void cpcommit() {
    asm volatile("cp.async.commit_group;\n" ::);
}
template<int W> __device__ __forceinline__ void cpwait() {
    asm volatile("cp.async.wait_group %0;\n" :: "n"(W));
}
__device__ __forceinline__ unsigned pack2(float lo, float hi) {
    unsigned d;
    asm("cvt.rn.f16x2.f32 %0, %1, %2;" : "=r"(d) : "f"(hi), "f"(lo));
    return d;
}
__device__ __forceinline__ void ldsm4(unsigned* r, unsigned a) {
    asm volatile("ldmatrix.sync.aligned.m8n8.x4.shared.b16 {%0,%1,%2,%3}, [%4];"
                 : "=r"(r[0]), "=r"(r[1]), "=r"(r[2]), "=r"(r[3]) : "r"(a));
}
__device__ __forceinline__ void mma16(float* d, const unsigned* a, const unsigned* b) {
    asm volatile("mma.sync.aligned.m16n8k16.row.col.f32.f16.f16.f32 "
                 "{%0,%1,%2,%3}, {%4,%5,%6,%7}, {%8,%9}, {%0,%1,%2,%3};"
                 : "+f"(d[0]), "+f"(d[1]), "+f"(d[2]), "+f"(d[3])
                 : "r"(a[0]), "r"(a[1]), "r"(a[2]), "r"(a[3]),
                   "r"(b[0]), "r"(b[1]));
}

// ------------------------------ prep (parallel) -----------------------------
// Block c in [0,79]: row c of Mredh. Block 80: bias vector.
__global__ void prep_kernel(const float* __restrict__ W_fc,
                            const float* __restrict__ b_fc,
                            const float* __restrict__ W_attn) {
    __shared__ float ws[256];
    const int c = blockIdx.x;
    const int tid = threadIdx.x;
    {
        int h = tid >> 6, o = tid & 63;
        ws[tid] = 0.25f * (W_attn[       h * 128 + o] +
                           W_attn[ 512 + h * 128 + o] +
                           W_attn[1024 + h * 128 + o] +
                           W_attn[1536 + h * 128 + o]);
    }
    __syncthreads();
    if (c < 64) {
        float v = W_fc[c * DD + tid] + W_fc[(64 + c) * DD + tid] +
                  W_fc[(128 + c) * DD + tid] + W_fc[(192 + c) * DD + tid];
        d_Mredh[c * DD + tid] = __float2half(v);
    } else if (c == 64) {
        float v0 = 0.f, v1 = 0.f, v2 = 0.f, v3 = 0.f;
        #pragma unroll
        for (int r = 0; r < 256; r += 4) {
            v0 += W_fc[(r + 0) * DD + tid] * ws[r + 0];
            v1 += W_fc[(r + 1) * DD + tid] * ws[r + 1];
            v2 += W_fc[(r + 2) * DD + tid] * ws[r + 2];
            v3 += W_fc[(r + 3) * DD + tid] * ws[r + 3];
        }
        d_Mredh[64 * DD + tid] = __float2half((v0 + v1) + (v2 + v3));
    } else if (c < 80) {
        d_Mredh[c * DD + tid] = __float2half(0.f);
    } else {
        if (tid < 64) {
            d_biasv[tid] = b_fc[tid] + b_fc[64 + tid] +
                           b_fc[128 + tid] + b_fc[192 + tid];
        } else if (tid == 64) {
            float v = 0.f;
            for (int r = 0; r < 256; r++) v += b_fc[r] * ws[r];
            d_biasv[64] = v;
        } else if (tid < NP) {
            d_biasv[tid] = 0.f;
        }
    }
}

// --------------------- unified pipelined fp16 GEMM -------------------------
// MODE 0: proj: acc = features[16384x256] @ Mredh^T; epilogue adds bias,
//         computes E=exp(col64) and writes g fp16 to d_gh (transform fused).
// MODE 1: agg:  acc = adj[4096x4096] @ gh^T; epilogue normalizes by col 64.
template<int MODE>
__global__ __launch_bounds__(THREADS, 1)
void gemm_kernel(const float* __restrict__ Abase, float* __restrict__ OutP)
{
    constexpr int lda = MODE ? NNODE : DD;     // floats
    constexpr int ldb = MODE ? NNODE : DD;     // halves
    constexpr int KT  = MODE ? NNODE / BK : DD / BK;

    extern __shared__ __align__(16) char sm[];
    float* Zs = (float*)(sm + OFF_Z);

    const int mtile = blockIdx.x, batch = blockIdx.y;
    const int tid = threadIdx.x;
    const int wid = tid >> 5, lane = tid & 31;
    const int wm = wid & 7, wn = wid >> 3;     // 8 m-warps x 2 n-warps
    const int g = lane >> 2, t = lane & 3;

    const float* A = Abase + (MODE ? (long)batch * NNODE * NNODE : 0L)
                           + (long)mtile * BM * lda;
    const __half* Bh = MODE ? (d_gh + (long)batch * NP * NNODE) : d_Mredh;

    const int ar = tid >> 3, ac = tid & 7;     // A chunk coords (rows 0..63)
    const int br = tid >> 2, bc = tid & 3;     // B chunk coords

    auto issue = [&](int s, int kt) {
        char* as = sm + s * A_STG;
        const float* ag = A + (long)kt * BK;
        #pragma unroll
        for (int q = 0; q < 2; q++) {
            int r = q * 64 + ar;
            cpa16(su32(as + r * (SWA * 4) + ac * 16), ag + (long)r * lda + ac * 4);
        }
        if (tid < 320) {
            char* bs = sm + OFF_B + s * B_STG;
            const __half* bg = Bh + (long)kt * BK;
            cpa16(su32(bs + br * SBB + bc * 16), bg + (long)br * ldb + bc * 8);
        }
    };

    float acc[5][4] = {};

    auto compute = [&](int s) {
        const float* as = (const float*)(sm + s * A_STG);
        const char*  bs = sm + OFF_B + s * B_STG;
        unsigned af[2][4], bf[5][4];
        unsigned b0 = su32(bs + (wn * 40 + (lane & 7)) * SBB + (lane >> 3) * 16);
        #pragma unroll
        for (int j = 0; j < 5; j++) ldsm4(bf[j], b0 + j * 8 * SBB);
        const float* pr = as + (wm * 16 + g) * SWA + 2 * t;
        #pragma unroll
        for (int kh = 0; kh < 2; kh++) {
            const float* p = pr + kh * 16;
            float2 v0 = *(const float2*)(p);
            float2 v1 = *(const float2*)(p + 8 * SWA);
            float2 v2 = *(const float2*)(p + 8);
            float2 v3 = *(const float2*)(p + 8 * SWA + 8);
            af[kh][0] = pack2(v0.x, v0.y);
            af[kh][1] = pack2(v1.x, v1.y);
            af[kh][2] = pack2(v2.x, v2.y);
            af[kh][3] = pack2(v3.x, v3.y);
        }
        #pragma unroll
        for (int kh = 0; kh < 2; kh++)
            #pragma unroll
            for (int j = 0; j < 5; j++)
                mma16(acc[j], af[kh], bf[j] + kh * 2);
    };

    #pragma unroll
    for (int s = 0; s < STAGES - 1; s++) { issue(s, s); cpcommit(); }

    for (int k = 0; k < KT; k++) {
        cpwait<STAGES - 2>();
        __syncthreads();
        if (k + STAGES - 1 < KT) issue((k + STAGES - 1) % STAGES, k + STAGES - 1);
        cpcommit();
        compute(k % STAGES);
    }

    // ------------------------------ epilogues ------------------------------
    if (MODE == 0) {
        const float b64 = d_biasv[64];
        if (wn == 1 && t == 0) {
            Zs[wm * 16 + g]     = acc[3][0] + b64;
            Zs[wm * 16 + g + 8] = acc[3][2] + b64;
        }
        __syncthreads();
        const int bb = (mtile * BM) >> 12;
        const int jbase = (mtile * BM) & (NNODE - 1);
        __half* gb = d_gh + (long)bb * NP * NNODE;
        {
            int rl0 = wm * 16 + g;
            float E0 = __expf(Zs[rl0]);
            float E1 = __expf(Zs[rl0 + 8]);
            int j0 = jbase + rl0, j1 = j0 + 8;
            #pragma unroll
            for (int j = 0; j < 5; j++) {
                int colb = wn * 40 + j * 8 + 2 * t;
                if (colb < 64) {
                    float c0 = d_biasv[colb], c1 = d_biasv[colb + 1];
                    gb[(long)colb * NNODE + j0]       = __float2half(E0 * (acc[j][0] + c0));
                    gb[(long)(colb + 1) * NNODE + j0] = __float2half(E0 * (acc[j][1] + c1));
                    gb[(long)colb * NNODE + j1]       = __float2half(E1 * (acc[j][2] + c0));
                    gb[(long)(colb + 1) * NNODE + j1] = __float2half(E1 * (acc[j][3] + c1));
                } else if (colb == 64) {
                    gb[64L * NNODE + j0] = __float2half(E0);
                    gb[64L * NNODE + j1] = __float2half(E1);
                }
            }
        }
    } else {
        if (wn == 1 && t == 0) {
            Zs[wm * 16 + g]     = acc[3][0];
            Zs[wm * 16 + g + 8] = acc[3][2];
        }
        __syncthreads();
        {
            int rl0 = wm * 16 + g;
            float rz0 = 1.0f / (4096.0f * Zs[rl0]);
            float rz1 = 1.0f / (4096.0f * Zs[rl0 + 8]);
            long ro0 = ((long)batch * NNODE + mtile * BM + rl0) * 64;
            long ro1 = ro0 + 8 * 64;
            #pragma unroll
            for (int j = 0; j < 5; j++) {
                int colb = wn * 40 + j * 8 + 2 * t;
                if (colb < 64) {
                    *(float2*)(OutP + ro0 + colb) =
                        make_float2(acc[j][0] * rz0, acc[j][1] * rz0);
                    *(float2*)(OutP + ro1 + colb) =
                        make_float2(acc[j][2] * rz1, acc[j][3] * rz1);
                }
            }
        }
    }
}

// ------------------------------ launch ------------------------------------
extern "C" void kernel_launch(void* const* d_in, const int* in_sizes, int n_in,
                              void* d_out, int out_size) {
    const float* features = (const float*)d_in[0];
    const float* adj      = (const float*)d_in[1];
    const float* W_fc     = (const float*)d_in[2];
    const float* b_fc     = (const float*)d_in[3];
    const float* W_attn   = (const float*)d_in[4];
    float* out = (float*)d_out;

    cudaFuncSetAttribute(gemm_kernel<0>,
                         cudaFuncAttributeMaxDynamicSharedMemorySize, SMEM_TOTAL);
    cudaFuncSetAttribute(gemm_kernel<1>,
                         cudaFuncAttributeMaxDynamicSharedMemorySize, SMEM_TOTAL);

    prep_kernel<<<81, 256>>>(W_fc, b_fc, W_attn);
    gemm_kernel<0><<<16384 / BM, THREADS, SMEM_TOTAL>>>(features, nullptr);
    gemm_kernel<1><<<dim3(NNODE / BM, BATCH), THREADS, SMEM_TOTAL>>>(adj, out);
}